// round 14
// baseline (speedup 1.0000x reference)
#include <cuda_runtime.h>
#include <cuda_fp16.h>
#include <math.h>
#include <stdint.h>

#define NN 100000
#define NE 1600000
#define CH 128          // channels = H*D
#define NH 4
#define HD 32
#define EPS 1e-5f
#define NB 98           // ceil(NN/1024) scan blocks
#define SPLIT_NODE 50048  // attn/final split point (multiple of 128)

// pair-layout strides (in float2 units)
#define LDA2 66   // As: row stride; banks 4g+2tg -> 2-way (optimal for 64-bit)
#define LDW2 136  // Wp: row stride; banks 16tg+2g -> 2-way (optimal)

// ---------------- scratch (device globals; no allocation allowed) ----------------
__device__ __align__(128) float g_q[NN * CH];
__device__ __align__(128) __half g_kv[NN * 2 * CH];  // per node: 32 chunks of [4 half k | 4 half v]
__device__ __align__(128) float g_sk[NN * CH];   // skip, then conv (in-place)
__device__ __align__(128) float g_stats[4 * CH]; // sum, sumsq, scale, shift
__device__ __align__(128) float g_wt[5 * CH * CH]; // tf32 weights in PAIR layout [64 p][128 n] float2
__device__ int g_cnt[NN];
__device__ int g_rowptr[NN + 1];
__device__ int g_cursor[NN];
__device__ int g_esrc[NE];
__device__ int g_blksum[128];
__device__ int g_blkoff[128];
__device__ int g_is64;

// ---------------- edge dtype detection (one warp, parallel) ----------------
__global__ void detect_k(const long long* __restrict__ ei) {
    int lane = threadIdx.x;
    int bad = 0;
    #pragma unroll
    for (int i = 0; i < 8; i++) {
        long long v = ei[lane + i * 32];
        bad |= (v < 0 || v >= NN) ? 1 : 0;
    }
    bad = __any_sync(0xffffffffu, bad);
    if (lane == 0) g_is64 = !bad;
}

__device__ __forceinline__ int edge_at(const void* ei, int idx) {
    return g_is64 ? (int)((const long long*)ei)[idx] : ((const int*)ei)[idx];
}

// ---------------- tf32 helpers ----------------
__device__ __forceinline__ float tf32r(float x) {
    uint32_t u;
    asm("cvt.rna.tf32.f32 %0, %1;" : "=r"(u) : "f"(x));
    return __uint_as_float(u);
}

// pre-round weights to tf32 AND convert to pair layout:
// g_wtp[m][p][n] = float2( W[(p>>2)*8 + (p&3)][n], W[(p>>2)*8 + (p&3) + 4][n] )
// Also zero bn accumulators (first 256 threads).
__global__ void prep_w_k(const float* __restrict__ Wq, const float* __restrict__ Wk,
                         const float* __restrict__ Wv, const float* __restrict__ Ws,
                         const float* __restrict__ Wfc) {
    int i = blockIdx.x * blockDim.x + threadIdx.x;   // float2 output index, total 5*8192
    if (i < 2 * CH) g_stats[i] = 0.f;
    if (i < 5 * 8192) {
        int m = i >> 13, r = i & 8191;
        int p = r >> 7, n = r & 127;
        int k0 = ((p >> 2) << 3) + (p & 3);
        const float* src;
        switch (m) {
            case 0: src = Wq; break;
            case 1: src = Wk; break;
            case 2: src = Wv; break;
            case 3: src = Ws; break;
            default: src = Wfc; break;
        }
        float2 w;
        w.x = tf32r(src[k0 * 128 + n]);
        w.y = tf32r(src[(k0 + 4) * 128 + n]);
        ((float2*)g_wt)[m * 8192 + r] = w;
    }
}

__global__ void zero_cnt_k() {
    int i = blockIdx.x * 1024 + threadIdx.x;
    if (i < NN) g_cnt[i] = 0;
}

// ---------------- batchnorm stats ----------------
__global__ void bn_stats_k(const float* __restrict__ x) {
    int c = threadIdx.x; // 128 threads
    float s = 0.f, sq = 0.f;
    for (int r = blockIdx.x; r < NN; r += gridDim.x) {
        float v = x[r * CH + c];
        s += v; sq += v * v;
    }
    atomicAdd(&g_stats[c], s);
    atomicAdd(&g_stats[CH + c], sq);
}

__global__ void bn_finalize_k(const float* __restrict__ gamma, const float* __restrict__ beta) {
    int c = threadIdx.x;
    float mean = g_stats[c] / (float)NN;
    float var = g_stats[CH + c] / (float)NN - mean * mean;
    float scale = gamma[c] * rsqrtf(var + EPS);
    g_stats[2 * CH + c] = scale;
    g_stats[3 * CH + c] = beta[c] - mean * scale;
}

// ---------------- CSR build ----------------
__global__ void hist_k(const void* __restrict__ ei) {
    int e = blockIdx.x * blockDim.x + threadIdx.x;
    if (e < NE) {
        int d = edge_at(ei, NE + e);
        if (d >= 0 && d < NN) atomicAdd(&g_cnt[d], 1);
    }
}

__global__ void block_scan_k() {
    __shared__ int warpsum[32];
    int t = threadIdx.x, lane = t & 31, wid = t >> 5;
    int i = blockIdx.x * 1024 + t;
    int v = (i < NN) ? g_cnt[i] : 0;
    int x = v;
    #pragma unroll
    for (int o = 1; o < 32; o <<= 1) {
        int y = __shfl_up_sync(0xffffffffu, x, o);
        if (lane >= o) x += y;
    }
    if (lane == 31) warpsum[wid] = x;
    __syncthreads();
    if (wid == 0) {
        int w = warpsum[lane];
        #pragma unroll
        for (int o = 1; o < 32; o <<= 1) {
            int y = __shfl_up_sync(0xffffffffu, w, o);
            if (lane >= o) w += y;
        }
        warpsum[lane] = w;
    }
    __syncthreads();
    int prefix = (wid > 0) ? warpsum[wid - 1] : 0;
    int incl = x + prefix;
    if (i < NN) g_rowptr[i] = incl - v;
    if (t == 1023) g_blksum[blockIdx.x] = incl;
}

__global__ void scan_totals_k() {
    __shared__ int warpsum[4];
    int t = threadIdx.x, lane = t & 31, wid = t >> 5; // 128 threads
    int v = (t < NB) ? g_blksum[t] : 0;
    int x = v;
    #pragma unroll
    for (int o = 1; o < 32; o <<= 1) {
        int y = __shfl_up_sync(0xffffffffu, x, o);
        if (lane >= o) x += y;
    }
    if (lane == 31) warpsum[wid] = x;
    __syncthreads();
    if (t == 0) {
        int a = 0;
        #pragma unroll
        for (int k = 0; k < 4; k++) { int b = warpsum[k]; warpsum[k] = a; a += b; }
        g_rowptr[NN] = a;
    }
    __syncthreads();
    if (t < NB) g_blkoff[t] = x - v + warpsum[wid];
}

__global__ void add_offsets_k() {
    int i = blockIdx.x * 1024 + threadIdx.x;
    if (i < NN) {
        int val = g_rowptr[i] + g_blkoff[blockIdx.x];
        g_rowptr[i] = val;
        g_cursor[i] = val;
    }
}

__global__ void scatter_k(const void* __restrict__ ei) {
    int e = blockIdx.x * blockDim.x + threadIdx.x;
    if (e < NE) {
        int d = edge_at(ei, NE + e);
        int s = edge_at(ei, e);
        if (d >= 0 && d < NN && s >= 0 && s < NN) {
            int pos = atomicAdd(&g_cursor[d], 1);
            if (pos >= 0 && pos < NE) g_esrc[pos] = s;
        }
    }
}

// ---------------- tf32 tensor-core GEMM (pair layout, 512 threads) ----------------
__device__ __forceinline__ void mma_tf32(float* c, const uint32_t* a, uint32_t b0, uint32_t b1) {
    asm volatile(
        "mma.sync.aligned.m16n8k8.row.col.f32.tf32.tf32.f32 "
        "{%0,%1,%2,%3}, {%4,%5,%6,%7}, {%8,%9}, {%0,%1,%2,%3};"
        : "+f"(c[0]), "+f"(c[1]), "+f"(c[2]), "+f"(c[3])
        : "r"(a[0]), "r"(a[1]), "r"(a[2]), "r"(a[3]), "r"(b0), "r"(b1));
}

__device__ __forceinline__ void cp16(uint32_t smem_dst, const void* gsrc) {
    asm volatile("cp.async.ca.shared.global [%0], [%1], 16;" :: "r"(smem_dst), "l"(gsrc));
}
__device__ __forceinline__ void cp_commit() { asm volatile("cp.async.commit_group;"); }
template <int N>
__device__ __forceinline__ void cp_wait() { asm volatile("cp.async.wait_group %0;" :: "n"(N)); }

// stage one weight tile (pair layout, 64x128 float2) via cp.async; 8 cp16 per thread (512 thr)
__device__ __forceinline__ void stage_w_async(const float2* __restrict__ Wsrc2, uint32_t wbuf_u32, int t) {
    #pragma unroll
    for (int i = 0; i < 8; i++) {
        int lin = i * 512 + t;          // 4096 chunks of 16B
        int p = lin >> 6, n2 = lin & 63;
        cp16(wbuf_u32 + (p * LDW2 + n2 * 2) * 8, Wsrc2 + p * 128 + n2 * 2);
    }
    cp_commit();
}

// compute 128x128 block: As pair [128][LDA2], Wp pair [64][LDW2]; warp tile 32x32 (16 warps)
// OUTMODE: 0 = fp32 plain, 1 = fp32 + residual, 2 = fp16 into g_kv (kvoff 0=k, 4=v)
template <int OUTMODE>
__device__ __forceinline__ void mma_compute_store(const float2* Asp, const float2* Wp,
                                                  const float* __restrict__ bias,
                                                  float* __restrict__ Out,
                                                  const float* __restrict__ resid,
                                                  int row0, int t, int kvoff) {
    const int lane = t & 31, wrp = t >> 5;      // wrp 0..15
    const int wm = wrp & 3, wn = wrp >> 2;      // m0 = wm*32, n0 = wn*32
    const int g = lane >> 2, tg = lane & 3;
    const int m0 = wm * 32, n0 = wn * 32;

    float acc[2][4][4];
    #pragma unroll
    for (int mi = 0; mi < 2; mi++)
        #pragma unroll
        for (int nj = 0; nj < 4; nj++)
            #pragma unroll
            for (int c = 0; c < 4; c++) acc[mi][nj][c] = 0.f;

    #pragma unroll
    for (int ks = 0; ks < 16; ks++) {
        const int p = ks * 4 + tg;
        uint32_t a[2][4];
        #pragma unroll
        for (int mi = 0; mi < 2; mi++) {
            float2 lo = Asp[(m0 + mi * 16 + g) * LDA2 + p];
            float2 hi = Asp[(m0 + mi * 16 + 8 + g) * LDA2 + p];
            a[mi][0] = __float_as_uint(lo.x);
            a[mi][1] = __float_as_uint(hi.x);
            a[mi][2] = __float_as_uint(lo.y);
            a[mi][3] = __float_as_uint(hi.y);
        }
        #pragma unroll
        for (int nj = 0; nj < 4; nj++) {
            float2 b = Wp[p * LDW2 + n0 + nj * 8 + g];
            uint32_t b0 = __float_as_uint(b.x);
            uint32_t b1 = __float_as_uint(b.y);
            mma_tf32(acc[0][nj], a[0], b0, b1);
            mma_tf32(acc[1][nj], a[1], b0, b1);
        }
    }

    #pragma unroll
    for (int mi = 0; mi < 2; mi++) {
        #pragma unroll
        for (int half_ = 0; half_ < 2; half_++) {
            int gr = row0 + m0 + mi * 16 + g + half_ * 8;
            if (gr < NN) {
                #pragma unroll
                for (int nj = 0; nj < 4; nj++) {
                    int col = n0 + nj * 8 + 2 * tg;
                    float c0 = acc[mi][nj][half_ * 2 + 0] + __ldg(&bias[col]);
                    float c1 = acc[mi][nj][half_ * 2 + 1] + __ldg(&bias[col + 1]);
                    if (OUTMODE == 1) {
                        float2 rr = *(const float2*)&resid[gr * 128 + col];
                        c0 += rr.x; c1 += rr.y;
                    }
                    if (OUTMODE == 2) {
                        int addr = gr * 256 + (col >> 2) * 8 + kvoff + (col & 3);
                        *(__half2*)&g_kv[addr] = __floats2half2_rn(c0, c1);
                    } else {
                        *(float2*)&Out[gr * 128 + col] = make_float2(c0, c1);
                    }
                }
            }
        }
    }
}

// stage a float4 of A into pair layout (slot = c4&1 selects .x/.y of 4 consecutive pairs)
__device__ __forceinline__ void store_a_pair(float* Af, int r, int c4, float4 a) {
    int base = (r * LDA2 + ((c4 >> 1) << 2)) * 2 + (c4 & 1);
    Af[base + 0] = a.x;
    Af[base + 2] = a.y;
    Af[base + 4] = a.z;
    Af[base + 6] = a.w;
}

// fused QKVS: 512 threads, stage A (BN+ReLU+tf32) once, cp.async double-buffered pair weights
__global__ void __launch_bounds__(512, 1) gemm_qkvs_fused_k(
    const float* __restrict__ x,
    const float* __restrict__ bq, const float* __restrict__ bk,
    const float* __restrict__ bv, const float* __restrict__ bs) {
    extern __shared__ float2 sm2[];
    float2* Asp = sm2;                                    // [128][LDA2]
    float2* Wb[2] = { sm2 + 128 * LDA2, sm2 + 128 * LDA2 + 64 * LDW2 };
    uint32_t wb_u32[2] = { (uint32_t)__cvta_generic_to_shared(Wb[0]),
                           (uint32_t)__cvta_generic_to_shared(Wb[1]) };
    const int t = threadIdx.x;
    const int row0 = blockIdx.x * 128;
    const float2* wt2 = (const float2*)g_wt;

    stage_w_async(wt2 + 0 * 8192, wb_u32[0], t);
    stage_w_async(wt2 + 1 * 8192, wb_u32[1], t);

    // stage A with fused BN+ReLU+tf32 into pair layout (8 float4 per thread)
    float* Af = (float*)Asp;
    #pragma unroll
    for (int i = 0; i < 8; i++) {
        int lin = i * 512 + t;
        int r = lin >> 5, c4 = lin & 31;
        int gr = row0 + r;
        float4 a = (gr < NN) ? ((const float4*)x)[gr * 32 + c4] : make_float4(0.f, 0.f, 0.f, 0.f);
        float4 sc = ((const float4*)(g_stats + 2 * CH))[c4];
        float4 sh = ((const float4*)(g_stats + 3 * CH))[c4];
        a.x = tf32r(fmaxf(0.f, a.x * sc.x + sh.x));
        a.y = tf32r(fmaxf(0.f, a.y * sc.y + sh.y));
        a.z = tf32r(fmaxf(0.f, a.z * sc.z + sh.z));
        a.w = tf32r(fmaxf(0.f, a.w * sc.w + sh.w));
        store_a_pair(Af, r, c4, a);
    }

    // i=0: q (W0 in buf0)
    cp_wait<1>(); __syncthreads();
    mma_compute_store<0>(Asp, Wb[0], bq, g_q, nullptr, row0, t, 0);
    __syncthreads();
    // i=1: k (W1 in buf1); prefetch W2 into buf0
    stage_w_async(wt2 + 2 * 8192, wb_u32[0], t);
    cp_wait<1>(); __syncthreads();
    mma_compute_store<2>(Asp, Wb[1], bk, nullptr, nullptr, row0, t, 0);
    __syncthreads();
    // i=2: v (W2 in buf0); prefetch W3 into buf1
    stage_w_async(wt2 + 3 * 8192, wb_u32[1], t);
    cp_wait<1>(); __syncthreads();
    mma_compute_store<2>(Asp, Wb[0], bv, nullptr, nullptr, row0, t, 4);
    __syncthreads();
    // i=3: skip (W3 in buf1)
    cp_wait<0>(); __syncthreads();
    mma_compute_store<0>(Asp, Wb[1], bs, g_sk, nullptr, row0, t, 0);
}

__global__ void __launch_bounds__(512, 1) gemm_final_k(
    const float* __restrict__ bfc, const float* __restrict__ x, float* __restrict__ out,
    int blk_off) {
    extern __shared__ float2 sm2[];
    float2* Asp = sm2;
    float2* Wp = sm2 + 128 * LDA2;
    uint32_t ws_u32 = (uint32_t)__cvta_generic_to_shared(Wp);
    const int t = threadIdx.x;
    const int row0 = (blockIdx.x + blk_off) * 128;

    stage_w_async((const float2*)g_wt + 4 * 8192, ws_u32, t);

    float* Af = (float*)Asp;
    #pragma unroll
    for (int i = 0; i < 8; i++) {
        int lin = i * 512 + t;
        int r = lin >> 5, c4 = lin & 31;
        int gr = row0 + r;
        float4 a = (gr < NN) ? ((const float4*)g_sk)[gr * 32 + c4] : make_float4(0.f, 0.f, 0.f, 0.f);
        a.x = tf32r(a.x); a.y = tf32r(a.y); a.z = tf32r(a.z); a.w = tf32r(a.w);
        store_a_pair(Af, r, c4, a);
    }
    cp_wait<0>(); __syncthreads();
    mma_compute_store<1>(Asp, Wp, bfc, out, x, row0, t, 0);
}

// ---------------- attention: warp-per-node, dual online-softmax accumulators ----------------
__global__ void attn_k(int node_off, int node_cnt) {
    int wi = (blockIdx.x * blockDim.x + threadIdx.x) >> 5;
    int lane = threadIdx.x & 31;
    if (wi >= node_cnt) return;
    int w = node_off + wi;
    const float inv = 0.17677669529663689f; // 1/sqrt(32)
    const int off = lane * 4;               // floats [4l,4l+4); head = lane>>3
    const int base = w * CH;

    float4 q4 = *(const float4*)&g_q[base + off];
    q4.x *= inv; q4.y *= inv; q4.z *= inv; q4.w *= inv;

    int beg = g_rowptr[w], end = g_rowptr[w + 1];

    float m0 = -1e30f, l0 = 0.f, m1 = -1e30f, l1 = 0.f;
    float4 A0 = make_float4(0.f, 0.f, 0.f, 0.f);
    float4 A1 = make_float4(0.f, 0.f, 0.f, 0.f);

    int e = beg;
    for (; e + 1 < end; e += 2) {
        int s0 = __ldg(&g_esrc[e]);
        int s1 = __ldg(&g_esrc[e + 1]);
        uint4 kv0 = *(const uint4*)&g_kv[s0 * 256 + lane * 8];
        uint4 kv1 = *(const uint4*)&g_kv[s1 * 256 + lane * 8];

        float2 ka0 = __half22float2(*(__half2*)&kv0.x);
        float2 kb0 = __half22float2(*(__half2*)&kv0.y);
        float2 ka1 = __half22float2(*(__half2*)&kv1.x);
        float2 kb1 = __half22float2(*(__half2*)&kv1.y);
        float t0 = q4.x * ka0.x + q4.y * ka0.y + q4.z * kb0.x + q4.w * kb0.y;
        float t1 = q4.x * ka1.x + q4.y * ka1.y + q4.z * kb1.x + q4.w * kb1.y;
        t0 += __shfl_xor_sync(0xffffffffu, t0, 1);
        t1 += __shfl_xor_sync(0xffffffffu, t1, 1);
        t0 += __shfl_xor_sync(0xffffffffu, t0, 2);
        t1 += __shfl_xor_sync(0xffffffffu, t1, 2);
        t0 += __shfl_xor_sync(0xffffffffu, t0, 4);
        t1 += __shfl_xor_sync(0xffffffffu, t1, 4);

        float2 va0 = __half22float2(*(__half2*)&kv0.z);
        float2 vb0 = __half22float2(*(__half2*)&kv0.w);
        float2 va1 = __half22float2(*(__half2*)&kv1.z);
        float2 vb1 = __half22float2(*(__half2*)&kv1.w);

        float nm0 = fmaxf(m0, t0);
        float nm1 = fmaxf(m1, t1);
        float sc0 = __expf(m0 - nm0), p0 = __expf(t0 - nm0);
        float sc1 = __expf(m1 - nm1), p1 = __expf(t1 - nm1);
        m0 = nm0; m1 = nm1;
        l0 = l0 * sc0 + p0;
        l1 = l1 * sc1 + p1;
        A0.x = A0.x * sc0 + p0 * va0.x;  A1.x = A1.x * sc1 + p1 * va1.x;
        A0.y = A0.y * sc0 + p0 * va0.y;  A1.y = A1.y * sc1 + p1 * va1.y;
        A0.z = A0.z * sc0 + p0 * vb0.x;  A1.z = A1.z * sc1 + p1 * vb1.x;
        A0.w = A0.w * sc0 + p0 * vb0.y;  A1.w = A1.w * sc1 + p1 * vb1.y;
    }
    if (e < end) {
        int s0 = __ldg(&g_esrc[e]);
        uint4 kv0 = *(const uint4*)&g_kv[s0 * 256 + lane * 8];
        float2 ka0 = __half22float2(*(__half2*)&kv0.x);
        float2 kb0 = __half22float2(*(__half2*)&kv0.y);
        float t0 = q4.x * ka0.x + q4.y * ka0.y + q4.z * kb0.x + q4.w * kb0.y;
        t0 += __shfl_xor_sync(0xffffffffu, t0, 1);
        t0 += __shfl_xor_sync(0xffffffffu, t0, 2);
        t0 += __shfl_xor_sync(0xffffffffu, t0, 4);
        float2 va0 = __half22float2(*(__half2*)&kv0.z);
        float2 vb0 = __half22float2(*(__half2*)&kv0.w);
        float nm0 = fmaxf(m0, t0);
        float sc0 = __expf(m0 - nm0), p0 = __expf(t0 - nm0);
        m0 = nm0;
        l0 = l0 * sc0 + p0;
        A0.x = A0.x * sc0 + p0 * va0.x;
        A0.y = A0.y * sc0 + p0 * va0.y;
        A0.z = A0.z * sc0 + p0 * vb0.x;
        A0.w = A0.w * sc0 + p0 * vb0.y;
    }

    float nm = fmaxf(m0, m1);
    float s0 = __expf(m0 - nm), s1 = __expf(m1 - nm);
    float l = l0 * s0 + l1 * s1;
    float4 acc;
    acc.x = A0.x * s0 + A1.x * s1;
    acc.y = A0.y * s0 + A1.y * s1;
    acc.z = A0.z * s0 + A1.z * s1;
    acc.w = A0.w * s0 + A1.w * s1;

    if (l > 0.f) {
        float r = 1.f / l;
        float4 o = *(float4*)&g_sk[base + off];
        o.x += acc.x * r;
        o.y += acc.y * r;
        o.z += acc.z * r;
        o.w += acc.w * r;
        *(float4*)&g_sk[base + off] = o;
    }
}

// ---------------- launch ----------------
extern "C" void kernel_launch(void* const* d_in, const int* in_sizes, int n_in,
                              void* d_out, int out_size) {
    const float* x         = (const float*)d_in[0];
    const void* ei         = d_in[1];
    const float* bn_gamma  = (const float*)d_in[2];
    const float* bn_beta   = (const float*)d_in[3];
    const float* Wq        = (const float*)d_in[4];
    const float* bq        = (const float*)d_in[5];
    const float* Wk        = (const float*)d_in[6];
    const float* bk        = (const float*)d_in[7];
    const float* Wv        = (const float*)d_in[8];
    const float* bv        = (const float*)d_in[9];
    const float* Wskip     = (const float*)d_in[10];
    const float* bskip     = (const float*)d_in[11];
    const float* Wfc       = (const float*)d_in[12];
    const float* bfc       = (const float*)d_in[13];
    float* out = (float*)d_out;

    static cudaStream_t s_side = nullptr;
    static cudaEvent_t ev_fork = nullptr, ev_join = nullptr, ev_attnA = nullptr, ev_finA = nullptr;
    if (s_side == nullptr) {
        cudaStreamCreateWithFlags(&s_side, cudaStreamNonBlocking);
        cudaEventCreateWithFlags(&ev_fork, cudaEventDisableTiming);
        cudaEventCreateWithFlags(&ev_join, cudaEventDisableTiming);
        cudaEventCreateWithFlags(&ev_attnA, cudaEventDisableTiming);
        cudaEventCreateWithFlags(&ev_finA, cudaEventDisableTiming);
    }

    const int SMEM_QKVS = (128 * LDA2 + 2 * 64 * LDW2) * 8;  // 206848 B
    const int SMEM_FIN  = (128 * LDA2 + 64 * LDW2) * 8;      // 137216 B
    cudaFuncSetAttribute(gemm_qkvs_fused_k, cudaFuncAttributeMaxDynamicSharedMemorySize, SMEM_QKVS);
    cudaFuncSetAttribute(gemm_final_k, cudaFuncAttributeMaxDynamicSharedMemorySize, SMEM_FIN);

    const int MBLK = (NN + 127) / 128;        // 782
    const int MBLK_A = SPLIT_NODE / 128;      // 391
    const int MBLK_B = MBLK - MBLK_A;         // 391
    const int NODES_A = SPLIT_NODE;
    const int NODES_B = NN - SPLIT_NODE;

    cudaEventRecord(ev_fork, 0);

    // main chain (qkvs stays the 4th submitted kernel -> ncu profiles it)
    prep_w_k<<<160, 256>>>(Wq, Wk, Wv, Wskip, Wfc);         // 1 (also zeroes bn stats)
    bn_stats_k<<<512, 128>>>(x);                            // 2
    bn_finalize_k<<<1, 128>>>(bn_gamma, bn_beta);           // 3
    gemm_qkvs_fused_k<<<MBLK, 512, SMEM_QKVS>>>(x, bq, bk, bv, bskip);  // 4

    // side chain: CSR build
    cudaStreamWaitEvent(s_side, ev_fork, 0);
    zero_cnt_k<<<NB, 1024, 0, s_side>>>();
    detect_k<<<1, 32, 0, s_side>>>((const long long*)ei);
    hist_k<<<(NE + 255) / 256, 256, 0, s_side>>>(ei);
    block_scan_k<<<NB, 1024, 0, s_side>>>();
    scan_totals_k<<<1, 128, 0, s_side>>>();
    add_offsets_k<<<NB, 1024, 0, s_side>>>();
    scatter_k<<<(NE + 255) / 256, 256, 0, s_side>>>(ei);
    cudaEventRecord(ev_join, s_side);

    // join + split attention / final for overlap
    cudaStreamWaitEvent(0, ev_join, 0);
    attn_k<<<(NODES_A * 32 + 255) / 256, 256>>>(0, NODES_A);
    cudaEventRecord(ev_attnA, 0);
    attn_k<<<(NODES_B * 32 + 255) / 256, 256>>>(SPLIT_NODE, NODES_B);

    cudaStreamWaitEvent(s_side, ev_attnA, 0);
    gemm_final_k<<<MBLK_A, 512, SMEM_FIN, s_side>>>(bfc, x, out, 0);
    cudaEventRecord(ev_finA, s_side);

    gemm_final_k<<<MBLK_B, 512, SMEM_FIN>>>(bfc, x, out, MBLK_A);
    cudaStreamWaitEvent(0, ev_finA, 0);
}

// round 15
// speedup vs baseline: 1.1324x; 1.1324x over previous
#include <cuda_runtime.h>
#include <cuda_fp16.h>
#include <math.h>
#include <stdint.h>

#define NN 100000
#define NE 1600000
#define CH 128          // channels = H*D
#define NH 4
#define HD 32
#define EPS 1e-5f
#define NB 98           // ceil(NN/1024) scan blocks
#define SPLIT_NODE 50048  // attn/final split point (multiple of 64)

#define LDA 132   // As row stride: bank = 4g+tg -> conflict-free A frag loads
#define LDW 136   // Ws row stride: bank = 8tg+8nj+g -> conflict-free B frag loads

// ---------------- scratch (device globals; no allocation allowed) ----------------
__device__ __align__(128) float g_q[NN * CH];
__device__ __align__(128) __half g_kv[NN * 2 * CH];  // per node: 32 chunks of [4 half k | 4 half v]
__device__ __align__(128) float g_sk[NN * CH];   // skip, then conv (in-place)
__device__ __align__(128) float g_stats[4 * CH]; // sum, sumsq, scale, shift
__device__ __align__(128) float g_wt[5 * CH * CH]; // tf32-prerounded Wq,Wk,Wv,Wskip,Wfc
__device__ int g_cnt[NN];
__device__ int g_rowptr[NN + 1];
__device__ int g_cursor[NN];
__device__ int g_esrc[NE];
__device__ int g_blksum[128];
__device__ int g_blkoff[128];
__device__ int g_is64;

// ---------------- edge dtype detection (one warp, parallel) ----------------
__global__ void detect_k(const long long* __restrict__ ei) {
    int lane = threadIdx.x;
    int bad = 0;
    #pragma unroll
    for (int i = 0; i < 8; i++) {
        long long v = ei[lane + i * 32];
        bad |= (v < 0 || v >= NN) ? 1 : 0;
    }
    bad = __any_sync(0xffffffffu, bad);
    if (lane == 0) g_is64 = !bad;
}

__device__ __forceinline__ int edge_at(const void* ei, int idx) {
    return g_is64 ? (int)((const long long*)ei)[idx] : ((const int*)ei)[idx];
}

// ---------------- tf32 helpers ----------------
__device__ __forceinline__ float tf32r(float x) {
    uint32_t u;
    asm("cvt.rna.tf32.f32 %0, %1;" : "=r"(u) : "f"(x));
    return __uint_as_float(u);
}

// pre-round all 5 weight matrices to tf32; also zero bn accumulators
__global__ void prep_w_k(const float* __restrict__ Wq, const float* __restrict__ Wk,
                         const float* __restrict__ Wv, const float* __restrict__ Ws,
                         const float* __restrict__ Wfc) {
    int i = blockIdx.x * blockDim.x + threadIdx.x;   // float4 index, total 5*4096
    if (i < 2 * CH) g_stats[i] = 0.f;
    if (i < 5 * 4096) {
        int m = i >> 12, idx = i & 4095;
        const float* src;
        switch (m) {
            case 0: src = Wq; break;
            case 1: src = Wk; break;
            case 2: src = Wv; break;
            case 3: src = Ws; break;
            default: src = Wfc; break;
        }
        float4 w = ((const float4*)src)[idx];
        w.x = tf32r(w.x); w.y = tf32r(w.y); w.z = tf32r(w.z); w.w = tf32r(w.w);
        ((float4*)g_wt)[m * 4096 + idx] = w;
    }
}

__global__ void zero_cnt_k() {
    int i = blockIdx.x * 1024 + threadIdx.x;
    if (i < NN) g_cnt[i] = 0;
}

// ---------------- batchnorm stats ----------------
__global__ void bn_stats_k(const float* __restrict__ x) {
    int c = threadIdx.x; // 128 threads
    float s = 0.f, sq = 0.f;
    for (int r = blockIdx.x; r < NN; r += gridDim.x) {
        float v = x[r * CH + c];
        s += v; sq += v * v;
    }
    atomicAdd(&g_stats[c], s);
    atomicAdd(&g_stats[CH + c], sq);
}

__global__ void bn_finalize_k(const float* __restrict__ gamma, const float* __restrict__ beta) {
    int c = threadIdx.x;
    float mean = g_stats[c] / (float)NN;
    float var = g_stats[CH + c] / (float)NN - mean * mean;
    float scale = gamma[c] * rsqrtf(var + EPS);
    g_stats[2 * CH + c] = scale;
    g_stats[3 * CH + c] = beta[c] - mean * scale;
}

// ---------------- CSR build ----------------
__global__ void hist_k(const void* __restrict__ ei) {
    int e = blockIdx.x * blockDim.x + threadIdx.x;
    if (e < NE) {
        int d = edge_at(ei, NE + e);
        if (d >= 0 && d < NN) atomicAdd(&g_cnt[d], 1);
    }
}

__global__ void block_scan_k() {
    __shared__ int warpsum[32];
    int t = threadIdx.x, lane = t & 31, wid = t >> 5;
    int i = blockIdx.x * 1024 + t;
    int v = (i < NN) ? g_cnt[i] : 0;
    int x = v;
    #pragma unroll
    for (int o = 1; o < 32; o <<= 1) {
        int y = __shfl_up_sync(0xffffffffu, x, o);
        if (lane >= o) x += y;
    }
    if (lane == 31) warpsum[wid] = x;
    __syncthreads();
    if (wid == 0) {
        int w = warpsum[lane];
        #pragma unroll
        for (int o = 1; o < 32; o <<= 1) {
            int y = __shfl_up_sync(0xffffffffu, w, o);
            if (lane >= o) w += y;
        }
        warpsum[lane] = w;
    }
    __syncthreads();
    int prefix = (wid > 0) ? warpsum[wid - 1] : 0;
    int incl = x + prefix;
    if (i < NN) g_rowptr[i] = incl - v;
    if (t == 1023) g_blksum[blockIdx.x] = incl;
}

__global__ void scan_totals_k() {
    __shared__ int warpsum[4];
    int t = threadIdx.x, lane = t & 31, wid = t >> 5; // 128 threads
    int v = (t < NB) ? g_blksum[t] : 0;
    int x = v;
    #pragma unroll
    for (int o = 1; o < 32; o <<= 1) {
        int y = __shfl_up_sync(0xffffffffu, x, o);
        if (lane >= o) x += y;
    }
    if (lane == 31) warpsum[wid] = x;
    __syncthreads();
    if (t == 0) {
        int a = 0;
        #pragma unroll
        for (int k = 0; k < 4; k++) { int b = warpsum[k]; warpsum[k] = a; a += b; }
        g_rowptr[NN] = a;
    }
    __syncthreads();
    if (t < NB) g_blkoff[t] = x - v + warpsum[wid];
}

__global__ void add_offsets_k() {
    int i = blockIdx.x * 1024 + threadIdx.x;
    if (i < NN) {
        int val = g_rowptr[i] + g_blkoff[blockIdx.x];
        g_rowptr[i] = val;
        g_cursor[i] = val;
    }
}

__global__ void scatter_k(const void* __restrict__ ei) {
    int e = blockIdx.x * blockDim.x + threadIdx.x;
    if (e < NE) {
        int d = edge_at(ei, NE + e);
        int s = edge_at(ei, e);
        if (d >= 0 && d < NN && s >= 0 && s < NN) {
            int pos = atomicAdd(&g_cursor[d], 1);
            if (pos >= 0 && pos < NE) g_esrc[pos] = s;
        }
    }
}

// ---------------- tf32 tensor-core GEMM: 64-row tiles, 2 CTAs/SM ----------------
__device__ __forceinline__ void mma_tf32(float* c, const uint32_t* a, uint32_t b0, uint32_t b1) {
    asm volatile(
        "mma.sync.aligned.m16n8k8.row.col.f32.tf32.tf32.f32 "
        "{%0,%1,%2,%3}, {%4,%5,%6,%7}, {%8,%9}, {%0,%1,%2,%3};"
        : "+f"(c[0]), "+f"(c[1]), "+f"(c[2]), "+f"(c[3])
        : "r"(a[0]), "r"(a[1]), "r"(a[2]), "r"(a[3]), "r"(b0), "r"(b1));
}

__device__ __forceinline__ void cp16(uint32_t smem_dst, const void* gsrc) {
    asm volatile("cp.async.ca.shared.global [%0], [%1], 16;" :: "r"(smem_dst), "l"(gsrc));
}
__device__ __forceinline__ void cp_commit() { asm volatile("cp.async.commit_group;"); }
template <int N>
__device__ __forceinline__ void cp_wait() { asm volatile("cp.async.wait_group %0;" :: "n"(N)); }

// stage one 128x128 tf32 weight tile into Ws via cp.async (256 threads, 16 cp16 each)
__device__ __forceinline__ void stage_w_async(const float* __restrict__ Wsrc, uint32_t wbuf_u32, int t) {
    #pragma unroll
    for (int i = 0; i < 16; i++) {
        int lin = i * 256 + t;
        int r = lin >> 5, c4 = lin & 31;
        cp16(wbuf_u32 + (r * LDW + c4 * 4) * 4, Wsrc + lin * 4);
    }
    cp_commit();
}

// compute 64x128 block: As [64][LDA], Ws [128][LDW]; 8 warps, warp tile 32x32 (wm 2 x wn 4)
// OUTMODE: 0 = fp32 plain, 1 = fp32 + residual, 2 = fp16 into g_kv (kvoff 0=k, 4=v)
template <int OUTMODE>
__device__ __forceinline__ void mma_compute_store(const float* As, const float* Ws,
                                                  const float* __restrict__ bias,
                                                  float* __restrict__ Out,
                                                  const float* __restrict__ resid,
                                                  int row0, int t, int kvoff) {
    const int lane = t & 31, wrp = t >> 5;
    const int wm = wrp & 1, wn = wrp >> 1;      // m0 = wm*32, n0 = wn*32
    const int g = lane >> 2, tg = lane & 3;
    const int m0 = wm * 32, n0 = wn * 32;

    float acc[2][4][4];
    #pragma unroll
    for (int mi = 0; mi < 2; mi++)
        #pragma unroll
        for (int nj = 0; nj < 4; nj++)
            #pragma unroll
            for (int c = 0; c < 4; c++) acc[mi][nj][c] = 0.f;

    #pragma unroll
    for (int ks = 0; ks < 16; ks++) {
        const int k0 = ks * 8;
        uint32_t a[2][4];
        #pragma unroll
        for (int mi = 0; mi < 2; mi++) {
            const float* p = As + (m0 + mi * 16 + g) * LDA + k0 + tg;
            a[mi][0] = __float_as_uint(p[0]);
            a[mi][1] = __float_as_uint(p[8 * LDA]);
            a[mi][2] = __float_as_uint(p[4]);
            a[mi][3] = __float_as_uint(p[8 * LDA + 4]);
        }
        #pragma unroll
        for (int nj = 0; nj < 4; nj++) {
            const float* qp = Ws + (k0 + tg) * LDW + n0 + nj * 8 + g;
            uint32_t b0 = __float_as_uint(qp[0]);
            uint32_t b1 = __float_as_uint(qp[4 * LDW]);
            mma_tf32(acc[0][nj], a[0], b0, b1);
            mma_tf32(acc[1][nj], a[1], b0, b1);
        }
    }

    #pragma unroll
    for (int mi = 0; mi < 2; mi++) {
        #pragma unroll
        for (int half_ = 0; half_ < 2; half_++) {
            int gr = row0 + m0 + mi * 16 + g + half_ * 8;
            if (gr < NN) {
                #pragma unroll
                for (int nj = 0; nj < 4; nj++) {
                    int col = n0 + nj * 8 + 2 * tg;
                    float c0 = acc[mi][nj][half_ * 2 + 0] + __ldg(&bias[col]);
                    float c1 = acc[mi][nj][half_ * 2 + 1] + __ldg(&bias[col + 1]);
                    if (OUTMODE == 1) {
                        float2 rr = *(const float2*)&resid[gr * 128 + col];
                        c0 += rr.x; c1 += rr.y;
                    }
                    if (OUTMODE == 2) {
                        int addr = gr * 256 + (col >> 2) * 8 + kvoff + (col & 3);
                        *(__half2*)&g_kv[addr] = __floats2half2_rn(c0, c1);
                    } else {
                        *(float2*)&Out[gr * 128 + col] = make_float2(c0, c1);
                    }
                }
            }
        }
    }
}

// fused QKVS: 64-row A tile staged once (BN+ReLU+tf32); single W buffer; 2 CTAs/SM
__global__ void __launch_bounds__(256, 2) gemm_qkvs_fused_k(
    const float* __restrict__ x,
    const float* __restrict__ bq, const float* __restrict__ bk,
    const float* __restrict__ bv, const float* __restrict__ bs) {
    extern __shared__ float sm[];
    float* As = sm;                 // [64][LDA]
    float* Ws = sm + 64 * LDA;      // [128][LDW]
    uint32_t ws_u32 = (uint32_t)__cvta_generic_to_shared(Ws);
    const int t = threadIdx.x;
    const int row0 = blockIdx.x * 64;

    // start staging W0 while we stage A
    stage_w_async(g_wt + 0 * 16384, ws_u32, t);

    // stage A with fused BN+ReLU+tf32 (64 rows x 32 float4 = 8 per thread)
    #pragma unroll
    for (int i = 0; i < 8; i++) {
        int lin = i * 256 + t;
        int r = lin >> 5, c4 = lin & 31;
        int gr = row0 + r;
        float4 a = (gr < NN) ? ((const float4*)x)[gr * 32 + c4] : make_float4(0.f, 0.f, 0.f, 0.f);
        float4 sc = ((const float4*)(g_stats + 2 * CH))[c4];
        float4 sh = ((const float4*)(g_stats + 3 * CH))[c4];
        a.x = tf32r(fmaxf(0.f, a.x * sc.x + sh.x));
        a.y = tf32r(fmaxf(0.f, a.y * sc.y + sh.y));
        a.z = tf32r(fmaxf(0.f, a.z * sc.z + sh.z));
        a.w = tf32r(fmaxf(0.f, a.w * sc.w + sh.w));
        *(float4*)&As[r * LDA + c4 * 4] = a;
    }

    #pragma unroll 1
    for (int wsel = 0; wsel < 4; wsel++) {
        cp_wait<0>(); __syncthreads();
        switch (wsel) {
            case 0: mma_compute_store<0>(As, Ws, bq, g_q, nullptr, row0, t, 0); break;
            case 1: mma_compute_store<2>(As, Ws, bk, nullptr, nullptr, row0, t, 0); break;
            case 2: mma_compute_store<2>(As, Ws, bv, nullptr, nullptr, row0, t, 4); break;
            default: mma_compute_store<0>(As, Ws, bs, g_sk, nullptr, row0, t, 0); break;
        }
        if (wsel < 3) {
            __syncthreads();   // all warps done reading Ws before restaging
            stage_w_async(g_wt + (wsel + 1) * 16384, ws_u32, t);
        }
    }
}

__global__ void __launch_bounds__(256, 2) gemm_final_k(
    const float* __restrict__ bfc, const float* __restrict__ x, float* __restrict__ out,
    int blk_off) {
    extern __shared__ float sm[];
    float* As = sm;
    float* Ws = sm + 64 * LDA;
    uint32_t ws_u32 = (uint32_t)__cvta_generic_to_shared(Ws);
    const int t = threadIdx.x;
    const int row0 = (blockIdx.x + blk_off) * 64;

    stage_w_async(g_wt + 4 * 16384, ws_u32, t);

    #pragma unroll
    for (int i = 0; i < 8; i++) {
        int lin = i * 256 + t;
        int r = lin >> 5, c4 = lin & 31;
        int gr = row0 + r;
        float4 a = (gr < NN) ? ((const float4*)g_sk)[gr * 32 + c4] : make_float4(0.f, 0.f, 0.f, 0.f);
        a.x = tf32r(a.x); a.y = tf32r(a.y); a.z = tf32r(a.z); a.w = tf32r(a.w);
        *(float4*)&As[r * LDA + c4 * 4] = a;
    }
    cp_wait<0>(); __syncthreads();
    mma_compute_store<1>(As, Ws, bfc, out, x, row0, t, 0);
}

// ---------------- attention: warp-per-node, dual online-softmax accumulators ----------------
__global__ void attn_k(int node_off, int node_cnt) {
    int wi = (blockIdx.x * blockDim.x + threadIdx.x) >> 5;
    int lane = threadIdx.x & 31;
    if (wi >= node_cnt) return;
    int w = node_off + wi;
    const float inv = 0.17677669529663689f; // 1/sqrt(32)
    const int off = lane * 4;               // floats [4l,4l+4); head = lane>>3
    const int base = w * CH;

    float4 q4 = *(const float4*)&g_q[base + off];
    q4.x *= inv; q4.y *= inv; q4.z *= inv; q4.w *= inv;

    int beg = g_rowptr[w], end = g_rowptr[w + 1];

    float m0 = -1e30f, l0 = 0.f, m1 = -1e30f, l1 = 0.f;
    float4 A0 = make_float4(0.f, 0.f, 0.f, 0.f);
    float4 A1 = make_float4(0.f, 0.f, 0.f, 0.f);

    int e = beg;
    for (; e + 1 < end; e += 2) {
        int s0 = __ldg(&g_esrc[e]);
        int s1 = __ldg(&g_esrc[e + 1]);
        uint4 kv0 = *(const uint4*)&g_kv[s0 * 256 + lane * 8];
        uint4 kv1 = *(const uint4*)&g_kv[s1 * 256 + lane * 8];

        float2 ka0 = __half22float2(*(__half2*)&kv0.x);
        float2 kb0 = __half22float2(*(__half2*)&kv0.y);
        float2 ka1 = __half22float2(*(__half2*)&kv1.x);
        float2 kb1 = __half22float2(*(__half2*)&kv1.y);
        float t0 = q4.x * ka0.x + q4.y * ka0.y + q4.z * kb0.x + q4.w * kb0.y;
        float t1 = q4.x * ka1.x + q4.y * ka1.y + q4.z * kb1.x + q4.w * kb1.y;
        t0 += __shfl_xor_sync(0xffffffffu, t0, 1);
        t1 += __shfl_xor_sync(0xffffffffu, t1, 1);
        t0 += __shfl_xor_sync(0xffffffffu, t0, 2);
        t1 += __shfl_xor_sync(0xffffffffu, t1, 2);
        t0 += __shfl_xor_sync(0xffffffffu, t0, 4);
        t1 += __shfl_xor_sync(0xffffffffu, t1, 4);

        float2 va0 = __half22float2(*(__half2*)&kv0.z);
        float2 vb0 = __half22float2(*(__half2*)&kv0.w);
        float2 va1 = __half22float2(*(__half2*)&kv1.z);
        float2 vb1 = __half22float2(*(__half2*)&kv1.w);

        float nm0 = fmaxf(m0, t0);
        float nm1 = fmaxf(m1, t1);
        float sc0 = __expf(m0 - nm0), p0 = __expf(t0 - nm0);
        float sc1 = __expf(m1 - nm1), p1 = __expf(t1 - nm1);
        m0 = nm0; m1 = nm1;
        l0 = l0 * sc0 + p0;
        l1 = l1 * sc1 + p1;
        A0.x = A0.x * sc0 + p0 * va0.x;  A1.x = A1.x * sc1 + p1 * va1.x;
        A0.y = A0.y * sc0 + p0 * va0.y;  A1.y = A1.y * sc1 + p1 * va1.y;
        A0.z = A0.z * sc0 + p0 * vb0.x;  A1.z = A1.z * sc1 + p1 * vb1.x;
        A0.w = A0.w * sc0 + p0 * vb0.y;  A1.w = A1.w * sc1 + p1 * vb1.y;
    }
    if (e < end) {
        int s0 = __ldg(&g_esrc[e]);
        uint4 kv0 = *(const uint4*)&g_kv[s0 * 256 + lane * 8];
        float2 ka0 = __half22float2(*(__half2*)&kv0.x);
        float2 kb0 = __half22float2(*(__half2*)&kv0.y);
        float t0 = q4.x * ka0.x + q4.y * ka0.y + q4.z * kb0.x + q4.w * kb0.y;
        t0 += __shfl_xor_sync(0xffffffffu, t0, 1);
        t0 += __shfl_xor_sync(0xffffffffu, t0, 2);
        t0 += __shfl_xor_sync(0xffffffffu, t0, 4);
        float2 va0 = __half22float2(*(__half2*)&kv0.z);
        float2 vb0 = __half22float2(*(__half2*)&kv0.w);
        float nm0 = fmaxf(m0, t0);
        float sc0 = __expf(m0 - nm0), p0 = __expf(t0 - nm0);
        m0 = nm0;
        l0 = l0 * sc0 + p0;
        A0.x = A0.x * sc0 + p0 * va0.x;
        A0.y = A0.y * sc0 + p0 * va0.y;
        A0.z = A0.z * sc0 + p0 * vb0.x;
        A0.w = A0.w * sc0 + p0 * vb0.y;
    }

    float nm = fmaxf(m0, m1);
    float s0 = __expf(m0 - nm), s1 = __expf(m1 - nm);
    float l = l0 * s0 + l1 * s1;
    float4 acc;
    acc.x = A0.x * s0 + A1.x * s1;
    acc.y = A0.y * s0 + A1.y * s1;
    acc.z = A0.z * s0 + A1.z * s1;
    acc.w = A0.w * s0 + A1.w * s1;

    if (l > 0.f) {
        float r = 1.f / l;
        float4 o = *(float4*)&g_sk[base + off];
        o.x += acc.x * r;
        o.y += acc.y * r;
        o.z += acc.z * r;
        o.w += acc.w * r;
        *(float4*)&g_sk[base + off] = o;
    }
}

// ---------------- launch ----------------
extern "C" void kernel_launch(void* const* d_in, const int* in_sizes, int n_in,
                              void* d_out, int out_size) {
    const float* x         = (const float*)d_in[0];
    const void* ei         = d_in[1];
    const float* bn_gamma  = (const float*)d_in[2];
    const float* bn_beta   = (const float*)d_in[3];
    const float* Wq        = (const float*)d_in[4];
    const float* bq        = (const float*)d_in[5];
    const float* Wk        = (const float*)d_in[6];
    const float* bk        = (const float*)d_in[7];
    const float* Wv        = (const float*)d_in[8];
    const float* bv        = (const float*)d_in[9];
    const float* Wskip     = (const float*)d_in[10];
    const float* bskip     = (const float*)d_in[11];
    const float* Wfc       = (const float*)d_in[12];
    const float* bfc       = (const float*)d_in[13];
    float* out = (float*)d_out;

    static cudaStream_t s_side = nullptr;
    static cudaEvent_t ev_fork = nullptr, ev_join = nullptr, ev_attnA = nullptr, ev_finA = nullptr;
    if (s_side == nullptr) {
        cudaStreamCreateWithFlags(&s_side, cudaStreamNonBlocking);
        cudaEventCreateWithFlags(&ev_fork, cudaEventDisableTiming);
        cudaEventCreateWithFlags(&ev_join, cudaEventDisableTiming);
        cudaEventCreateWithFlags(&ev_attnA, cudaEventDisableTiming);
        cudaEventCreateWithFlags(&ev_finA, cudaEventDisableTiming);
    }

    const int SMEM_G = (64 * LDA + 128 * LDW) * 4;   // 103424 B -> 2 CTAs/SM
    cudaFuncSetAttribute(gemm_qkvs_fused_k, cudaFuncAttributeMaxDynamicSharedMemorySize, SMEM_G);
    cudaFuncSetAttribute(gemm_final_k, cudaFuncAttributeMaxDynamicSharedMemorySize, SMEM_G);

    const int MBLK64 = (NN + 63) / 64;        // 1563
    const int MBLK_A = SPLIT_NODE / 64;       // 782
    const int MBLK_B = MBLK64 - MBLK_A;       // 781
    const int NODES_A = SPLIT_NODE;
    const int NODES_B = NN - SPLIT_NODE;

    cudaEventRecord(ev_fork, 0);

    // main chain (qkvs stays the 4th submitted kernel -> ncu profiles it)
    prep_w_k<<<80, 256>>>(Wq, Wk, Wv, Wskip, Wfc);          // 1 (also zeroes bn stats)
    bn_stats_k<<<512, 128>>>(x);                            // 2
    bn_finalize_k<<<1, 128>>>(bn_gamma, bn_beta);           // 3
    gemm_qkvs_fused_k<<<MBLK64, 256, SMEM_G>>>(x, bq, bk, bv, bskip);  // 4

    // side chain: CSR build
    cudaStreamWaitEvent(s_side, ev_fork, 0);
    zero_cnt_k<<<NB, 1024, 0, s_side>>>();
    detect_k<<<1, 32, 0, s_side>>>((const long long*)ei);
    hist_k<<<(NE + 255) / 256, 256, 0, s_side>>>(ei);
    block_scan_k<<<NB, 1024, 0, s_side>>>();
    scan_totals_k<<<1, 128, 0, s_side>>>();
    add_offsets_k<<<NB, 1024, 0, s_side>>>();
    scatter_k<<<(NE + 255) / 256, 256, 0, s_side>>>(ei);
    cudaEventRecord(ev_join, s_side);

    // join + split attention / final for overlap
    cudaStreamWaitEvent(0, ev_join, 0);
    attn_k<<<(NODES_A * 32 + 255) / 256, 256>>>(0, NODES_A);
    cudaEventRecord(ev_attnA, 0);
    attn_k<<<(NODES_B * 32 + 255) / 256, 256>>>(SPLIT_NODE, NODES_B);

    cudaStreamWaitEvent(s_side, ev_attnA, 0);
    gemm_final_k<<<MBLK_A, 256, SMEM_G, s_side>>>(bfc, x, out, 0);
    cudaEventRecord(ev_finA, s_side);

    gemm_final_k<<<MBLK_B, 256, SMEM_G>>>(bfc, x, out, MBLK_A);
    cudaStreamWaitEvent(0, ev_finA, 0);
}

// round 16
// speedup vs baseline: 1.3667x; 1.2069x over previous
#include <cuda_runtime.h>
#include <cuda_fp16.h>
#include <math.h>
#include <stdint.h>

#define NN 100000
#define NE 1600000
#define CH 128          // channels = H*D
#define NH 4
#define HD 32
#define EPS 1e-5f
#define NB 98           // ceil(NN/1024) scan blocks
#define SPLIT_NODE 50048  // attn/final split point (multiple of 128)

#define LDAH 68    // Ah row stride in half2 units: bank 4g+tg -> conflict-free
#define LDWH 136   // Wh row stride in half2 units: bank 8tg+g -> conflict-free

// ---------------- scratch (device globals; no allocation allowed) ----------------
__device__ __align__(128) float g_q[NN * CH];
__device__ __align__(128) __half g_kv[NN * 2 * CH];  // per node: 32 chunks of [4 half k | 4 half v]
__device__ __align__(128) float g_sk[NN * CH];   // skip, then conv (in-place)
__device__ __align__(128) float g_stats[4 * CH]; // sum, sumsq, scale, shift
__device__ __align__(128) __half2 g_wh[5 * 64 * CH]; // fp16 weights pair layout: wh[m][p][n]=(W[2p][n],W[2p+1][n])
__device__ int g_cnt[NN];
__device__ int g_rowptr[NN + 1];
__device__ int g_cursor[NN];
__device__ int g_esrc[NE];
__device__ int g_blksum[128];
__device__ int g_blkoff[128];
__device__ int g_is64;

// ---------------- edge dtype detection (one warp, parallel) ----------------
__global__ void detect_k(const long long* __restrict__ ei) {
    int lane = threadIdx.x;
    int bad = 0;
    #pragma unroll
    for (int i = 0; i < 8; i++) {
        long long v = ei[lane + i * 32];
        bad |= (v < 0 || v >= NN) ? 1 : 0;
    }
    bad = __any_sync(0xffffffffu, bad);
    if (lane == 0) g_is64 = !bad;
}

__device__ __forceinline__ int edge_at(const void* ei, int idx) {
    return g_is64 ? (int)((const long long*)ei)[idx] : ((const int*)ei)[idx];
}

// pre-convert all 5 weight matrices to fp16 pair layout; also zero bn accumulators
__global__ void prep_w_k(const float* __restrict__ Wq, const float* __restrict__ Wk,
                         const float* __restrict__ Wv, const float* __restrict__ Ws,
                         const float* __restrict__ Wfc) {
    int i = blockIdx.x * blockDim.x + threadIdx.x;   // half2 output index, total 5*8192
    if (i < 2 * CH) g_stats[i] = 0.f;
    if (i < 5 * 8192) {
        int m = i >> 13, r = i & 8191;
        int p = r >> 7, n = r & 127;
        const float* src;
        switch (m) {
            case 0: src = Wq; break;
            case 1: src = Wk; break;
            case 2: src = Wv; break;
            case 3: src = Ws; break;
            default: src = Wfc; break;
        }
        g_wh[i] = __floats2half2_rn(src[(2 * p) * 128 + n], src[(2 * p + 1) * 128 + n]);
    }
}

__global__ void zero_cnt_k() {
    int i = blockIdx.x * 1024 + threadIdx.x;
    if (i < NN) g_cnt[i] = 0;
}

// ---------------- batchnorm stats ----------------
__global__ void bn_stats_k(const float* __restrict__ x) {
    int c = threadIdx.x; // 128 threads
    float s = 0.f, sq = 0.f;
    for (int r = blockIdx.x; r < NN; r += gridDim.x) {
        float v = x[r * CH + c];
        s += v; sq += v * v;
    }
    atomicAdd(&g_stats[c], s);
    atomicAdd(&g_stats[CH + c], sq);
}

__global__ void bn_finalize_k(const float* __restrict__ gamma, const float* __restrict__ beta) {
    int c = threadIdx.x;
    float mean = g_stats[c] / (float)NN;
    float var = g_stats[CH + c] / (float)NN - mean * mean;
    float scale = gamma[c] * rsqrtf(var + EPS);
    g_stats[2 * CH + c] = scale;
    g_stats[3 * CH + c] = beta[c] - mean * scale;
}

// ---------------- CSR build ----------------
__global__ void hist_k(const void* __restrict__ ei) {
    int e = blockIdx.x * blockDim.x + threadIdx.x;
    if (e < NE) {
        int d = edge_at(ei, NE + e);
        if (d >= 0 && d < NN) atomicAdd(&g_cnt[d], 1);
    }
}

__global__ void block_scan_k() {
    __shared__ int warpsum[32];
    int t = threadIdx.x, lane = t & 31, wid = t >> 5;
    int i = blockIdx.x * 1024 + t;
    int v = (i < NN) ? g_cnt[i] : 0;
    int x = v;
    #pragma unroll
    for (int o = 1; o < 32; o <<= 1) {
        int y = __shfl_up_sync(0xffffffffu, x, o);
        if (lane >= o) x += y;
    }
    if (lane == 31) warpsum[wid] = x;
    __syncthreads();
    if (wid == 0) {
        int w = warpsum[lane];
        #pragma unroll
        for (int o = 1; o < 32; o <<= 1) {
            int y = __shfl_up_sync(0xffffffffu, w, o);
            if (lane >= o) w += y;
        }
        warpsum[lane] = w;
    }
    __syncthreads();
    int prefix = (wid > 0) ? warpsum[wid - 1] : 0;
    int incl = x + prefix;
    if (i < NN) g_rowptr[i] = incl - v;
    if (t == 1023) g_blksum[blockIdx.x] = incl;
}

__global__ void scan_totals_k() {
    __shared__ int warpsum[4];
    int t = threadIdx.x, lane = t & 31, wid = t >> 5; // 128 threads
    int v = (t < NB) ? g_blksum[t] : 0;
    int x = v;
    #pragma unroll
    for (int o = 1; o < 32; o <<= 1) {
        int y = __shfl_up_sync(0xffffffffu, x, o);
        if (lane >= o) x += y;
    }
    if (lane == 31) warpsum[wid] = x;
    __syncthreads();
    if (t == 0) {
        int a = 0;
        #pragma unroll
        for (int k = 0; k < 4; k++) { int b = warpsum[k]; warpsum[k] = a; a += b; }
        g_rowptr[NN] = a;
    }
    __syncthreads();
    if (t < NB) g_blkoff[t] = x - v + warpsum[wid];
}

__global__ void add_offsets_k() {
    int i = blockIdx.x * 1024 + threadIdx.x;
    if (i < NN) {
        int val = g_rowptr[i] + g_blkoff[blockIdx.x];
        g_rowptr[i] = val;
        g_cursor[i] = val;
    }
}

__global__ void scatter_k(const void* __restrict__ ei) {
    int e = blockIdx.x * blockDim.x + threadIdx.x;
    if (e < NE) {
        int d = edge_at(ei, NE + e);
        int s = edge_at(ei, e);
        if (d >= 0 && d < NN && s >= 0 && s < NN) {
            int pos = atomicAdd(&g_cursor[d], 1);
            if (pos >= 0 && pos < NE) g_esrc[pos] = s;
        }
    }
}

// ---------------- fp16 tensor-core GEMM (m16n8k16, fp32 accum) ----------------
__device__ __forceinline__ void mma_f16(float* c, const uint32_t* a, uint32_t b0, uint32_t b1) {
    asm volatile(
        "mma.sync.aligned.m16n8k16.row.col.f32.f16.f16.f32 "
        "{%0,%1,%2,%3}, {%4,%5,%6,%7}, {%8,%9}, {%0,%1,%2,%3};"
        : "+f"(c[0]), "+f"(c[1]), "+f"(c[2]), "+f"(c[3])
        : "r"(a[0]), "r"(a[1]), "r"(a[2]), "r"(a[3]), "r"(b0), "r"(b1));
}

__device__ __forceinline__ void cp16(uint32_t smem_dst, const void* gsrc) {
    asm volatile("cp.async.ca.shared.global [%0], [%1], 16;" :: "r"(smem_dst), "l"(gsrc));
}
__device__ __forceinline__ void cp_commit() { asm volatile("cp.async.commit_group;"); }
template <int N>
__device__ __forceinline__ void cp_wait() { asm volatile("cp.async.wait_group %0;" :: "n"(N)); }

// stage one W tile (64 pair-rows x 128 n half2 = 32KB) via cp.async (256 thr, 8 cp16 each)
__device__ __forceinline__ void stage_w_async(const __half2* __restrict__ Wsrc, uint32_t wbuf_u32, int t) {
    #pragma unroll
    for (int i = 0; i < 8; i++) {
        int lin = i * 256 + t;          // 2048 chunks of 16B (4 half2)
        int p = lin >> 5, n4 = lin & 31;
        cp16(wbuf_u32 + (p * LDWH + n4 * 4) * 4, Wsrc + p * 128 + n4 * 4);
    }
    cp_commit();
}

// compute 128x128 block: Ah [128][LDAH] half2, Wh [64][LDWH] half2; 8 warps, warp tile 32x64
// OUTMODE: 0 = fp32 plain, 1 = fp32 + residual, 2 = fp16 into g_kv (kvoff 0=k, 4=v)
template <int OUTMODE>
__device__ __forceinline__ void mma_compute_store(const __half2* Ah, const __half2* Wh,
                                                  const float* __restrict__ bias,
                                                  float* __restrict__ Out,
                                                  const float* __restrict__ resid,
                                                  int row0, int t, int kvoff) {
    const int lane = t & 31, wrp = t >> 5;
    const int wm = wrp & 3, wn = wrp >> 2;      // m0 = wm*32, n0 = wn*64
    const int g = lane >> 2, tg = lane & 3;
    const int m0 = wm * 32, n0 = wn * 64;

    float acc[2][8][4];
    #pragma unroll
    for (int mi = 0; mi < 2; mi++)
        #pragma unroll
        for (int nj = 0; nj < 8; nj++)
            #pragma unroll
            for (int c = 0; c < 4; c++) acc[mi][nj][c] = 0.f;

    #pragma unroll
    for (int ks = 0; ks < 8; ks++) {
        const int pb = ks * 8;
        uint32_t a[2][4];
        #pragma unroll
        for (int mi = 0; mi < 2; mi++) {
            const __half2* pA = Ah + (m0 + mi * 16 + g) * LDAH + pb + tg;
            a[mi][0] = *(const uint32_t*)(pA);
            a[mi][1] = *(const uint32_t*)(pA + 8 * LDAH);
            a[mi][2] = *(const uint32_t*)(pA + 4);
            a[mi][3] = *(const uint32_t*)(pA + 8 * LDAH + 4);
        }
        #pragma unroll
        for (int nj = 0; nj < 8; nj++) {
            const __half2* pB = Wh + (pb + tg) * LDWH + n0 + nj * 8 + g;
            uint32_t b0 = *(const uint32_t*)(pB);
            uint32_t b1 = *(const uint32_t*)(pB + 4 * LDWH);
            mma_f16(acc[0][nj], a[0], b0, b1);
            mma_f16(acc[1][nj], a[1], b0, b1);
        }
    }

    #pragma unroll
    for (int mi = 0; mi < 2; mi++) {
        #pragma unroll
        for (int half_ = 0; half_ < 2; half_++) {
            int gr = row0 + m0 + mi * 16 + g + half_ * 8;
            if (gr < NN) {
                #pragma unroll
                for (int nj = 0; nj < 8; nj++) {
                    int col = n0 + nj * 8 + 2 * tg;
                    float c0 = acc[mi][nj][half_ * 2 + 0] + __ldg(&bias[col]);
                    float c1 = acc[mi][nj][half_ * 2 + 1] + __ldg(&bias[col + 1]);
                    if (OUTMODE == 1) {
                        float2 rr = *(const float2*)&resid[gr * 128 + col];
                        c0 += rr.x; c1 += rr.y;
                    }
                    if (OUTMODE == 2) {
                        int addr = gr * 256 + (col >> 2) * 8 + kvoff + (col & 3);
                        *(__half2*)&g_kv[addr] = __floats2half2_rn(c0, c1);
                    } else {
                        *(float2*)&Out[gr * 128 + col] = make_float2(c0, c1);
                    }
                }
            }
        }
    }
}

// fused QKVS: stage A (BN+ReLU->fp16) once; cp.async double-buffered fp16 weights; 2 CTAs/SM
__global__ void __launch_bounds__(256, 2) gemm_qkvs_fused_k(
    const float* __restrict__ x,
    const float* __restrict__ bq, const float* __restrict__ bk,
    const float* __restrict__ bv, const float* __restrict__ bs) {
    extern __shared__ __half2 smh[];
    __half2* Ah = smh;                                   // [128][LDAH]
    __half2* Wb[2] = { smh + 128 * LDAH, smh + 128 * LDAH + 64 * LDWH };
    uint32_t wb_u32[2] = { (uint32_t)__cvta_generic_to_shared(Wb[0]),
                           (uint32_t)__cvta_generic_to_shared(Wb[1]) };
    const int t = threadIdx.x;
    const int row0 = blockIdx.x * 128;

    stage_w_async(g_wh + 0 * 8192, wb_u32[0], t);
    stage_w_async(g_wh + 1 * 8192, wb_u32[1], t);

    // stage A: BN+ReLU then fp16; float4 -> 2 consecutive half2 (pairs (4c4,4c4+1),(4c4+2,4c4+3))
    #pragma unroll
    for (int i = 0; i < 16; i++) {
        int lin = i * 256 + t;
        int r = lin >> 5, c4 = lin & 31;
        int gr = row0 + r;
        float4 a = (gr < NN) ? ((const float4*)x)[gr * 32 + c4] : make_float4(0.f, 0.f, 0.f, 0.f);
        float4 sc = ((const float4*)(g_stats + 2 * CH))[c4];
        float4 sh = ((const float4*)(g_stats + 3 * CH))[c4];
        a.x = fmaxf(0.f, a.x * sc.x + sh.x);
        a.y = fmaxf(0.f, a.y * sc.y + sh.y);
        a.z = fmaxf(0.f, a.z * sc.z + sh.z);
        a.w = fmaxf(0.f, a.w * sc.w + sh.w);
        __half2* dst = Ah + r * LDAH + 2 * c4;
        dst[0] = __floats2half2_rn(a.x, a.y);
        dst[1] = __floats2half2_rn(a.z, a.w);
    }

    // i=0: q (W0 in buf0)
    cp_wait<1>(); __syncthreads();
    mma_compute_store<0>(Ah, Wb[0], bq, g_q, nullptr, row0, t, 0);
    __syncthreads();
    // i=1: k (W1 in buf1); prefetch W2 into buf0
    stage_w_async(g_wh + 2 * 8192, wb_u32[0], t);
    cp_wait<1>(); __syncthreads();
    mma_compute_store<2>(Ah, Wb[1], bk, nullptr, nullptr, row0, t, 0);
    __syncthreads();
    // i=2: v (W2 in buf0); prefetch W3 into buf1
    stage_w_async(g_wh + 3 * 8192, wb_u32[1], t);
    cp_wait<1>(); __syncthreads();
    mma_compute_store<2>(Ah, Wb[0], bv, nullptr, nullptr, row0, t, 4);
    __syncthreads();
    // i=3: skip (W3 in buf1)
    cp_wait<0>(); __syncthreads();
    mma_compute_store<0>(Ah, Wb[1], bs, g_sk, nullptr, row0, t, 0);
}

__global__ void __launch_bounds__(256, 2) gemm_final_k(
    const float* __restrict__ bfc, const float* __restrict__ x, float* __restrict__ out,
    int blk_off) {
    extern __shared__ __half2 smh[];
    __half2* Ah = smh;
    __half2* Wh = smh + 128 * LDAH;
    uint32_t ws_u32 = (uint32_t)__cvta_generic_to_shared(Wh);
    const int t = threadIdx.x;
    const int row0 = (blockIdx.x + blk_off) * 128;

    stage_w_async(g_wh + 4 * 8192, ws_u32, t);

    #pragma unroll
    for (int i = 0; i < 16; i++) {
        int lin = i * 256 + t;
        int r = lin >> 5, c4 = lin & 31;
        int gr = row0 + r;
        float4 a = (gr < NN) ? ((const float4*)g_sk)[gr * 32 + c4] : make_float4(0.f, 0.f, 0.f, 0.f);
        __half2* dst = Ah + r * LDAH + 2 * c4;
        dst[0] = __floats2half2_rn(a.x, a.y);
        dst[1] = __floats2half2_rn(a.z, a.w);
    }
    cp_wait<0>(); __syncthreads();
    mma_compute_store<1>(Ah, Wh, bfc, out, x, row0, t, 0);
}

// ---------------- attention: warp-per-node, dual online-softmax accumulators ----------------
__global__ void attn_k(int node_off, int node_cnt) {
    int wi = (blockIdx.x * blockDim.x + threadIdx.x) >> 5;
    int lane = threadIdx.x & 31;
    if (wi >= node_cnt) return;
    int w = node_off + wi;
    const float inv = 0.17677669529663689f; // 1/sqrt(32)
    const int off = lane * 4;               // floats [4l,4l+4); head = lane>>3
    const int base = w * CH;

    float4 q4 = *(const float4*)&g_q[base + off];
    q4.x *= inv; q4.y *= inv; q4.z *= inv; q4.w *= inv;

    int beg = g_rowptr[w], end = g_rowptr[w + 1];

    float m0 = -1e30f, l0 = 0.f, m1 = -1e30f, l1 = 0.f;
    float4 A0 = make_float4(0.f, 0.f, 0.f, 0.f);
    float4 A1 = make_float4(0.f, 0.f, 0.f, 0.f);

    int e = beg;
    for (; e + 1 < end; e += 2) {
        int s0 = __ldg(&g_esrc[e]);
        int s1 = __ldg(&g_esrc[e + 1]);
        uint4 kv0 = *(const uint4*)&g_kv[s0 * 256 + lane * 8];
        uint4 kv1 = *(const uint4*)&g_kv[s1 * 256 + lane * 8];

        float2 ka0 = __half22float2(*(__half2*)&kv0.x);
        float2 kb0 = __half22float2(*(__half2*)&kv0.y);
        float2 ka1 = __half22float2(*(__half2*)&kv1.x);
        float2 kb1 = __half22float2(*(__half2*)&kv1.y);
        float t0 = q4.x * ka0.x + q4.y * ka0.y + q4.z * kb0.x + q4.w * kb0.y;
        float t1 = q4.x * ka1.x + q4.y * ka1.y + q4.z * kb1.x + q4.w * kb1.y;
        t0 += __shfl_xor_sync(0xffffffffu, t0, 1);
        t1 += __shfl_xor_sync(0xffffffffu, t1, 1);
        t0 += __shfl_xor_sync(0xffffffffu, t0, 2);
        t1 += __shfl_xor_sync(0xffffffffu, t1, 2);
        t0 += __shfl_xor_sync(0xffffffffu, t0, 4);
        t1 += __shfl_xor_sync(0xffffffffu, t1, 4);

        float2 va0 = __half22float2(*(__half2*)&kv0.z);
        float2 vb0 = __half22float2(*(__half2*)&kv0.w);
        float2 va1 = __half22float2(*(__half2*)&kv1.z);
        float2 vb1 = __half22float2(*(__half2*)&kv1.w);

        float nm0 = fmaxf(m0, t0);
        float nm1 = fmaxf(m1, t1);
        float sc0 = __expf(m0 - nm0), p0 = __expf(t0 - nm0);
        float sc1 = __expf(m1 - nm1), p1 = __expf(t1 - nm1);
        m0 = nm0; m1 = nm1;
        l0 = l0 * sc0 + p0;
        l1 = l1 * sc1 + p1;
        A0.x = A0.x * sc0 + p0 * va0.x;  A1.x = A1.x * sc1 + p1 * va1.x;
        A0.y = A0.y * sc0 + p0 * va0.y;  A1.y = A1.y * sc1 + p1 * va1.y;
        A0.z = A0.z * sc0 + p0 * vb0.x;  A1.z = A1.z * sc1 + p1 * vb1.x;
        A0.w = A0.w * sc0 + p0 * vb0.y;  A1.w = A1.w * sc1 + p1 * vb1.y;
    }
    if (e < end) {
        int s0 = __ldg(&g_esrc[e]);
        uint4 kv0 = *(const uint4*)&g_kv[s0 * 256 + lane * 8];
        float2 ka0 = __half22float2(*(__half2*)&kv0.x);
        float2 kb0 = __half22float2(*(__half2*)&kv0.y);
        float t0 = q4.x * ka0.x + q4.y * ka0.y + q4.z * kb0.x + q4.w * kb0.y;
        t0 += __shfl_xor_sync(0xffffffffu, t0, 1);
        t0 += __shfl_xor_sync(0xffffffffu, t0, 2);
        t0 += __shfl_xor_sync(0xffffffffu, t0, 4);
        float2 va0 = __half22float2(*(__half2*)&kv0.z);
        float2 vb0 = __half22float2(*(__half2*)&kv0.w);
        float nm0 = fmaxf(m0, t0);
        float sc0 = __expf(m0 - nm0), p0 = __expf(t0 - nm0);
        m0 = nm0;
        l0 = l0 * sc0 + p0;
        A0.x = A0.x * sc0 + p0 * va0.x;
        A0.y = A0.y * sc0 + p0 * va0.y;
        A0.z = A0.z * sc0 + p0 * vb0.x;
        A0.w = A0.w * sc0 + p0 * vb0.y;
    }

    float nm = fmaxf(m0, m1);
    float s0 = __expf(m0 - nm), s1 = __expf(m1 - nm);
    float l = l0 * s0 + l1 * s1;
    float4 acc;
    acc.x = A0.x * s0 + A1.x * s1;
    acc.y = A0.y * s0 + A1.y * s1;
    acc.z = A0.z * s0 + A1.z * s1;
    acc.w = A0.w * s0 + A1.w * s1;

    if (l > 0.f) {
        float r = 1.f / l;
        float4 o = *(float4*)&g_sk[base + off];
        o.x += acc.x * r;
        o.y += acc.y * r;
        o.z += acc.z * r;
        o.w += acc.w * r;
        *(float4*)&g_sk[base + off] = o;
    }
}

// ---------------- launch ----------------
extern "C" void kernel_launch(void* const* d_in, const int* in_sizes, int n_in,
                              void* d_out, int out_size) {
    const float* x         = (const float*)d_in[0];
    const void* ei         = d_in[1];
    const float* bn_gamma  = (const float*)d_in[2];
    const float* bn_beta   = (const float*)d_in[3];
    const float* Wq        = (const float*)d_in[4];
    const float* bq        = (const float*)d_in[5];
    const float* Wk        = (const float*)d_in[6];
    const float* bk        = (const float*)d_in[7];
    const float* Wv        = (const float*)d_in[8];
    const float* bv        = (const float*)d_in[9];
    const float* Wskip     = (const float*)d_in[10];
    const float* bskip     = (const float*)d_in[11];
    const float* Wfc       = (const float*)d_in[12];
    const float* bfc       = (const float*)d_in[13];
    float* out = (float*)d_out;

    static cudaStream_t s_side = nullptr;
    static cudaEvent_t ev_fork = nullptr, ev_join = nullptr, ev_attnA = nullptr, ev_finA = nullptr;
    if (s_side == nullptr) {
        cudaStreamCreateWithFlags(&s_side, cudaStreamNonBlocking);
        cudaEventCreateWithFlags(&ev_fork, cudaEventDisableTiming);
        cudaEventCreateWithFlags(&ev_join, cudaEventDisableTiming);
        cudaEventCreateWithFlags(&ev_attnA, cudaEventDisableTiming);
        cudaEventCreateWithFlags(&ev_finA, cudaEventDisableTiming);
    }

    const int SMEM_QKVS = (128 * LDAH + 2 * 64 * LDWH) * 4;  // 104448 B -> 2 CTAs/SM
    const int SMEM_FIN  = (128 * LDAH + 64 * LDWH) * 4;      // 69632 B
    cudaFuncSetAttribute(gemm_qkvs_fused_k, cudaFuncAttributeMaxDynamicSharedMemorySize, SMEM_QKVS);
    cudaFuncSetAttribute(gemm_final_k, cudaFuncAttributeMaxDynamicSharedMemorySize, SMEM_FIN);

    const int MBLK = (NN + 127) / 128;        // 782
    const int MBLK_A = SPLIT_NODE / 128;      // 391
    const int MBLK_B = MBLK - MBLK_A;         // 391
    const int NODES_A = SPLIT_NODE;
    const int NODES_B = NN - SPLIT_NODE;

    cudaEventRecord(ev_fork, 0);

    // main chain (qkvs stays the 4th submitted kernel -> ncu profiles it)
    prep_w_k<<<160, 256>>>(Wq, Wk, Wv, Wskip, Wfc);         // 1 (also zeroes bn stats)
    bn_stats_k<<<512, 128>>>(x);                            // 2
    bn_finalize_k<<<1, 128>>>(bn_gamma, bn_beta);           // 3
    gemm_qkvs_fused_k<<<MBLK, 256, SMEM_QKVS>>>(x, bq, bk, bv, bskip);  // 4

    // side chain: CSR build
    cudaStreamWaitEvent(s_side, ev_fork, 0);
    zero_cnt_k<<<NB, 1024, 0, s_side>>>();
    detect_k<<<1, 32, 0, s_side>>>((const long long*)ei);
    hist_k<<<(NE + 255) / 256, 256, 0, s_side>>>(ei);
    block_scan_k<<<NB, 1024, 0, s_side>>>();
    scan_totals_k<<<1, 128, 0, s_side>>>();
    add_offsets_k<<<NB, 1024, 0, s_side>>>();
    scatter_k<<<(NE + 255) / 256, 256, 0, s_side>>>(ei);
    cudaEventRecord(ev_join, s_side);

    // join + split attention / final for overlap
    cudaStreamWaitEvent(0, ev_join, 0);
    attn_k<<<(NODES_A * 32 + 255) / 256, 256>>>(0, NODES_A);
    cudaEventRecord(ev_attnA, 0);
    attn_k<<<(NODES_B * 32 + 255) / 256, 256>>>(SPLIT_NODE, NODES_B);

    cudaStreamWaitEvent(s_side, ev_attnA, 0);
    gemm_final_k<<<MBLK_A, 256, SMEM_FIN, s_side>>>(bfc, x, out, 0);
    cudaEventRecord(ev_finA, s_side);

    gemm_final_k<<<MBLK_B, 256, SMEM_FIN>>>(bfc, x, out, MBLK_A);
    cudaStreamWaitEvent(0, ev_finA, 0);
}